// round 14
// baseline (speedup 1.0000x reference)
#include <cuda_runtime.h>
#include <math.h>

// PatternBranch fused kernel — Round 14
// R13 + even/odd accumulator-chain split (8 independent FFMA2 chains),
// bw4 loads moved post-conv (funds the extra accumulator regs),
// carried smem addressing.

#define NTHREADS 256
#define SMEM_ROW_F 196                 // 65 cols * 3 ch = 195, padded to 196
#define SMEM_FLOATS (65 * SMEM_ROW_F)
#define SMEM_BYTES (SMEM_FLOATS * 4)
#define ROW_BYTES (SMEM_ROW_F * 4)     // 784 (16B-aligned row stride)

__device__ float4 g_bw4[1024 * 128];   // (b0, b1, b2, folded pat weight)

__device__ __forceinline__ void lds128v2(unsigned a,
                                         unsigned long long& p0,
                                         unsigned long long& p1) {
    asm volatile("ld.shared.v2.b64 {%0,%1}, [%2];"
                 : "=l"(p0), "=l"(p1) : "r"(a));
}
__device__ __forceinline__ unsigned long long pk2(float x, float y) {
    unsigned long long r;
    asm("mov.b64 %0, {%1,%2};" : "=l"(r) : "f"(x), "f"(y));
    return r;
}
__device__ __forceinline__ void upk2(unsigned long long v, float& x, float& y) {
    asm("mov.b64 {%0,%1}, %2;" : "=f"(x), "=f"(y) : "l"(v));
}
__device__ __forceinline__ unsigned long long ffma2(
    unsigned long long a, unsigned long long b, unsigned long long c) {
    unsigned long long d;
    asm("fma.rn.f32x2 %0, %1, %2, %3;" : "=l"(d) : "l"(a), "l"(b), "l"(c));
    return d;
}
__device__ __forceinline__ unsigned long long fadd2(
    unsigned long long a, unsigned long long b) {
    unsigned long long d;
    asm("add.rn.f32x2 %0, %1, %2;" : "=l"(d) : "l"(a), "l"(b));
    return d;
}

// ---- Prologue: build fused (base_w, pat) float4 table ----
__global__ void __launch_bounds__(256) prep_kernel(
    const float* __restrict__ base_w,   // [1024*128, 3]
    const float* __restrict__ pat_w,    // [1024*32]
    const int*   __restrict__ psi)      // [32]
{
    const int idx = blockIdx.x * blockDim.x + threadIdx.x;  // 131072
    const int pos = idx >> 7;
    const int c   = idx & 127;
    const float b0 = base_w[idx * 3 + 0];
    const float b1 = base_w[idx * 3 + 1];
    const float b2 = base_w[idx * 3 + 2];
    float pw = 0.f;
#pragma unroll
    for (int k = 0; k < 32; ++k)
        if (psi[k] == c) pw += pat_w[pos * 32 + k];
    g_bw4[idx] = make_float4(b0, b1, b2, pw);
}

// ---- Main fused kernel ----
__global__ void __launch_bounds__(NTHREADS, 2) pattern_branch_kernel(
    const float* __restrict__ g_in,     // [256,64,64,3]
    const float* __restrict__ conv_w,   // [3,3,3,128]
    const float* __restrict__ conv_b,   // [128]
    const float* __restrict__ match_w,  // [128]
    const float* __restrict__ match_b,  // [1]
    const float* __restrict__ pat_b,    // [1]
    const float* __restrict__ base_b,   // [3]
    float* __restrict__ out)            // [256,3]
{
    extern __shared__ float in_s[];
    __shared__ float red[8][5];

    const int tid = threadIdx.x;
    const int b   = blockIdx.x;

    // ---- Stage input sample into smem, zero-padding row 64 and col 64 ----
    float4* s4 = reinterpret_cast<float4*>(in_s);
    for (int i = tid; i < 65 + 48; i += NTHREADS) {
        if (i < 65) s4[i * 49 + 48] = make_float4(0.f, 0.f, 0.f, 0.f);
        else        s4[64 * 49 + (i - 65)] = make_float4(0.f, 0.f, 0.f, 0.f);
    }
    const float4* g4 = reinterpret_cast<const float4*>(g_in + (size_t)b * 12288);
    for (int i = tid; i < 64 * 48; i += NTHREADS) {
        int r = i / 48;
        int q = i - r * 48;
        s4[r * 49 + q] = g4[r * 48 + q];
    }

    // ---- Per-thread setup ----
    const int c0  = tid & 63;
    const int c1  = c0 + 64;
    const int grp = tid >> 6;

    // Packed conv weights: per row kh, 5 pairs: (w0,w1)(w2,w3)(w4,w5)(w6,w7)(w8,0).
    unsigned long long wp0[15], wp1[15];
#pragma unroll
    for (int kh = 0; kh < 3; ++kh) {
#pragma unroll
        for (int p = 0; p < 4; ++p) {
            int j = kh * 9 + 2 * p;
            wp0[kh * 5 + p] = pk2(conv_w[j * 128 + c0], conv_w[(j + 1) * 128 + c0]);
            wp1[kh * 5 + p] = pk2(conv_w[j * 128 + c1], conv_w[(j + 1) * 128 + c1]);
        }
        wp0[kh * 5 + 4] = pk2(conv_w[(kh * 9 + 8) * 128 + c0], 0.f);
        wp1[kh * 5 + 4] = pk2(conv_w[(kh * 9 + 8) * 128 + c1], 0.f);
    }
    // conv bias folded into the even-chain init: (cb, 0)
    const unsigned long long cbp0 = pk2(conv_b[c0], 0.f);
    const unsigned long long cbp1 = pk2(conv_b[c1], 0.f);

    const unsigned sbase = (unsigned)__cvta_generic_to_shared(in_s);

    __syncthreads();

    // ---- Main loop: 8 output rows x 16 position-pairs ----
    float fsum0 = 0.f, fsum1 = 0.f;
    float pacc  = 0.f;
    float ba0 = 0.f, ba1 = 0.f, ba2 = 0.f;

    const float4* __restrict__ bwp = g_bw4 + (grp * 256) * 128;

    const int ohBase = grp * 8;
    for (int oh = 0; oh < 8; ++oh) {
        unsigned rowa = sbase + (unsigned)(((ohBase + oh) * 2) * ROW_BYTES);
#pragma unroll 4
        for (int owp = 0; owp < 16; ++owp) {
            // 8 independent FFMA2 chains: (pos A/B) x (ch 0/1) x (even/odd pairs)
            unsigned long long aA0e = cbp0, aA1e = cbp1, aB0e = cbp0, aB1e = cbp1;
            unsigned long long aA0o = 0ull, aA1o = 0ull, aB0o = 0ull, aB1o = 0ull;
            unsigned ra = rowa;
#pragma unroll
            for (int kh = 0; kh < 3; ++kh) {
                unsigned long long v0, v1, v2, v3, v4, v5, v6, v7;
                lds128v2(ra,      v0, v1);
                lds128v2(ra + 16, v2, v3);
                lds128v2(ra + 32, v4, v5);
                lds128v2(ra + 48, v6, v7);
                ra += ROW_BYTES;
                // pos A even: p0(v0), p2(v2), p4(v4); odd: p1(v1), p3(v3)
                aA0e = ffma2(v0, wp0[kh * 5 + 0], aA0e);
                aA1e = ffma2(v0, wp1[kh * 5 + 0], aA1e);
                aA0o = ffma2(v1, wp0[kh * 5 + 1], aA0o);
                aA1o = ffma2(v1, wp1[kh * 5 + 1], aA1o);
                aA0e = ffma2(v2, wp0[kh * 5 + 2], aA0e);
                aA1e = ffma2(v2, wp1[kh * 5 + 2], aA1e);
                aA0o = ffma2(v3, wp0[kh * 5 + 3], aA0o);
                aA1o = ffma2(v3, wp1[kh * 5 + 3], aA1o);
                aA0e = ffma2(v4, wp0[kh * 5 + 4], aA0e);
                aA1e = ffma2(v4, wp1[kh * 5 + 4], aA1e);
                // pos B even: p0(v3), p2(v5), p4(v7); odd: p1(v4), p3(v6)
                aB0e = ffma2(v3, wp0[kh * 5 + 0], aB0e);
                aB1e = ffma2(v3, wp1[kh * 5 + 0], aB1e);
                aB0o = ffma2(v4, wp0[kh * 5 + 1], aB0o);
                aB1o = ffma2(v4, wp1[kh * 5 + 1], aB1o);
                aB0e = ffma2(v5, wp0[kh * 5 + 2], aB0e);
                aB1e = ffma2(v5, wp1[kh * 5 + 2], aB1e);
                aB0o = ffma2(v6, wp0[kh * 5 + 3], aB0o);
                aB1o = ffma2(v6, wp1[kh * 5 + 3], aB1o);
                aB0e = ffma2(v7, wp0[kh * 5 + 4], aB0e);
                aB1e = ffma2(v7, wp1[kh * 5 + 4], aB1e);
            }
            rowa += 48;

            // bw4 loads AFTER conv (L1-resident table; frees regs during conv)
            const float4 bA0 = __ldg(bwp + c0);
            const float4 bA1 = __ldg(bwp + c1);
            const float4 bB0 = __ldg(bwp + 128 + c0);
            const float4 bB1 = __ldg(bwp + 128 + c1);
            bwp += 256;

            // combine even/odd, horizontal add, relu
            const unsigned long long aA0 = fadd2(aA0e, aA0o);
            const unsigned long long aA1 = fadd2(aA1e, aA1o);
            const unsigned long long aB0 = fadd2(aB0e, aB0o);
            const unsigned long long aB1 = fadd2(aB1e, aB1o);
            float lA0, hA0, lA1, hA1, lB0, hB0, lB1, hB1;
            upk2(aA0, lA0, hA0);
            upk2(aA1, lA1, hA1);
            upk2(aB0, lB0, hB0);
            upk2(aB1, lB1, hB1);
            const float fA0 = fmaxf(lA0 + hA0, 0.f);
            const float fA1 = fmaxf(lA1 + hA1, 0.f);
            const float fB0 = fmaxf(lB0 + hB0, 0.f);
            const float fB1 = fmaxf(lB1 + hB1, 0.f);

            fsum0 += fA0 + fB0;
            fsum1 += fA1 + fB1;

            ba0 = fmaf(fA0, bA0.x, ba0);  ba1 = fmaf(fA0, bA0.y, ba1);
            ba2 = fmaf(fA0, bA0.z, ba2);  pacc = fmaf(fA0, bA0.w, pacc);
            ba0 = fmaf(fA1, bA1.x, ba0);  ba1 = fmaf(fA1, bA1.y, ba1);
            ba2 = fmaf(fA1, bA1.z, ba2);  pacc = fmaf(fA1, bA1.w, pacc);
            ba0 = fmaf(fB0, bB0.x, ba0);  ba1 = fmaf(fB0, bB0.y, ba1);
            ba2 = fmaf(fB0, bB0.z, ba2);  pacc = fmaf(fB0, bB0.w, pacc);
            ba0 = fmaf(fB1, bB1.x, ba0);  ba1 = fmaf(fB1, bB1.y, ba1);
            ba2 = fmaf(fB1, bB1.z, ba2);  pacc = fmaf(fB1, bB1.w, pacc);
        }
    }

    // ---- Block reduction of 5 scalars (deterministic tree) ----
    float v0 = fsum0 * match_w[c0] + fsum1 * match_w[c1];
    float v1 = pacc, v2 = ba0, v3 = ba1, v4 = ba2;
#pragma unroll
    for (int off = 16; off > 0; off >>= 1) {
        v0 += __shfl_down_sync(0xffffffffu, v0, off);
        v1 += __shfl_down_sync(0xffffffffu, v1, off);
        v2 += __shfl_down_sync(0xffffffffu, v2, off);
        v3 += __shfl_down_sync(0xffffffffu, v3, off);
        v4 += __shfl_down_sync(0xffffffffu, v4, off);
    }
    const int warp = tid >> 5;
    const int lane = tid & 31;
    if (lane == 0) {
        red[warp][0] = v0; red[warp][1] = v1; red[warp][2] = v2;
        red[warp][3] = v3; red[warp][4] = v4;
    }
    __syncthreads();

    if (tid == 0) {
        float s0 = 0.f, s1 = 0.f, s2 = 0.f, s3 = 0.f, s4v = 0.f;
#pragma unroll
        for (int w = 0; w < 8; ++w) {
            s0 += red[w][0]; s1 += red[w][1]; s2 += red[w][2];
            s3 += red[w][3]; s4v += red[w][4];
        }
        const float matchv = s0 * (1.0f / 1024.0f) + match_b[0];
        const float plog = s1 + pat_b[0];
        const float pp = 1.0f / (1.0f + expf(-plog));
        const float l0 = s2 + base_b[0];
        const float l1 = s3 + base_b[1];
        const float l2 = s4v + base_b[2];
        const float mx = fmaxf(l0, fmaxf(l1, l2));
        const float e0 = expf(l0 - mx);
        const float e1 = expf(l1 - mx);
        const float e2 = expf(l2 - mx);
        const float inv = 1.0f / (e0 + e1 + e2);

        float o0, o1, o2;
        if (matchv > 0.0f && plog >= 0.0f) {
            o0 = pp;
            o1 = 0.5f * (1.0f - pp);
            o2 = o1;
        } else {
            o0 = e0 * inv;
            o1 = e1 * inv;
            o2 = e2 * inv;
        }
        out[b * 3 + 0] = o0;
        out[b * 3 + 1] = o1;
        out[b * 3 + 2] = o2;
    }
}

extern "C" void kernel_launch(void* const* d_in, const int* in_sizes, int n_in,
                              void* d_out, int out_size)
{
    (void)in_sizes; (void)n_in; (void)out_size;
    const float* g_in    = (const float*)d_in[0];
    const float* conv_w  = (const float*)d_in[1];
    const float* conv_b  = (const float*)d_in[2];
    const float* match_w = (const float*)d_in[3];
    const float* match_b = (const float*)d_in[4];
    const float* pat_w   = (const float*)d_in[5];
    const float* pat_b   = (const float*)d_in[6];
    const float* base_w  = (const float*)d_in[7];
    const float* base_b  = (const float*)d_in[8];
    const int*   psi     = (const int*)d_in[9];
    float* out = (float*)d_out;

    cudaFuncSetAttribute(pattern_branch_kernel,
                         cudaFuncAttributeMaxDynamicSharedMemorySize, SMEM_BYTES);

    prep_kernel<<<512, 256>>>(base_w, pat_w, psi);

    pattern_branch_kernel<<<256, NTHREADS, SMEM_BYTES>>>(
        g_in, conv_w, conv_b, match_w, match_b,
        pat_b, base_b, out);
}

// round 15
// speedup vs baseline: 1.0584x; 1.0584x over previous
#include <cuda_runtime.h>
#include <math.h>

// PatternBranch fused — Round 15
// R13 inner body (best: 72.2us) + quarter-sample blocks (grid 1024) for SM load
// balance, partials combined by a tiny second kernel.

#define NTHREADS 256
#define SMEM_ROW_F 196                 // 65 cols * 3 ch = 195, padded to 196
#define N_STAGE_ROWS 17                // input rows per quarter (incl. overlap)
#define SMEM_FLOATS (N_STAGE_ROWS * SMEM_ROW_F)
#define SMEM_BYTES (SMEM_FLOATS * 4)   // 13328 B
#define ROW_BYTES (SMEM_ROW_F * 4)     // 784 (16B-aligned row stride)

__device__ float4 g_bw4[1024 * 128];   // (b0, b1, b2, folded pat weight)
__device__ float  g_part[1024 * 5];    // per-(sample,quarter) partials

__device__ __forceinline__ void lds128v2(unsigned a,
                                         unsigned long long& p0,
                                         unsigned long long& p1) {
    asm volatile("ld.shared.v2.b64 {%0,%1}, [%2];"
                 : "=l"(p0), "=l"(p1) : "r"(a));
}
__device__ __forceinline__ unsigned long long pk2(float x, float y) {
    unsigned long long r;
    asm("mov.b64 %0, {%1,%2};" : "=l"(r) : "f"(x), "f"(y));
    return r;
}
__device__ __forceinline__ void upk2(unsigned long long v, float& x, float& y) {
    asm("mov.b64 {%0,%1}, %2;" : "=f"(x), "=f"(y) : "l"(v));
}
__device__ __forceinline__ unsigned long long ffma2(
    unsigned long long a, unsigned long long b, unsigned long long c) {
    unsigned long long d;
    asm("fma.rn.f32x2 %0, %1, %2, %3;" : "=l"(d) : "l"(a), "l"(b), "l"(c));
    return d;
}

// ---- Prologue: build fused (base_w, pat) float4 table ----
__global__ void __launch_bounds__(256) prep_kernel(
    const float* __restrict__ base_w,   // [1024*128, 3]
    const float* __restrict__ pat_w,    // [1024*32]
    const int*   __restrict__ psi)      // [32]
{
    const int idx = blockIdx.x * blockDim.x + threadIdx.x;  // 131072
    const int pos = idx >> 7;
    const int c   = idx & 127;
    const float b0 = base_w[idx * 3 + 0];
    const float b1 = base_w[idx * 3 + 1];
    const float b2 = base_w[idx * 3 + 2];
    float pw = 0.f;
#pragma unroll
    for (int k = 0; k < 32; ++k)
        if (psi[k] == c) pw += pat_w[pos * 32 + k];
    g_bw4[idx] = make_float4(b0, b1, b2, pw);
}

// ---- Main fused kernel: one block per (sample, quarter) ----
__global__ void __launch_bounds__(NTHREADS, 2) pattern_branch_kernel(
    const float* __restrict__ g_in,     // [256,64,64,3]
    const float* __restrict__ conv_w,   // [3,3,3,128]
    const float* __restrict__ conv_b,   // [128]
    const float* __restrict__ match_w)  // [128]
{
    extern __shared__ float in_s[];
    __shared__ float red[8][5];

    const int tid = threadIdx.x;
    const int b   = blockIdx.x >> 2;    // sample
    const int qq  = blockIdx.x & 3;     // quarter (8 oh rows)

    // ---- Stage input rows [16qq, 16qq+16] into smem (17 rows, padded) ----
    float4* s4 = reinterpret_cast<float4*>(in_s);
    const float4* g4 = reinterpret_cast<const float4*>(g_in + (size_t)b * 12288);
    const int grBase = 16 * qq;
    for (int i = tid; i < N_STAGE_ROWS * 49; i += NTHREADS) {
        const int r = i / 49;
        const int q = i - r * 49;
        const int gr = grBase + r;
        if (q == 48 || gr >= 64) s4[i] = make_float4(0.f, 0.f, 0.f, 0.f);
        else                     s4[i] = g4[gr * 48 + q];
    }

    // ---- Per-thread setup ----
    const int c0  = tid & 63;
    const int c1  = c0 + 64;
    const int grp = tid >> 6;

    // Packed conv weights: per row kh, 5 pairs: (w0,w1)(w2,w3)(w4,w5)(w6,w7)(w8,0).
    unsigned long long wp0[15], wp1[15];
#pragma unroll
    for (int kh = 0; kh < 3; ++kh) {
#pragma unroll
        for (int p = 0; p < 4; ++p) {
            int j = kh * 9 + 2 * p;
            wp0[kh * 5 + p] = pk2(conv_w[j * 128 + c0], conv_w[(j + 1) * 128 + c0]);
            wp1[kh * 5 + p] = pk2(conv_w[j * 128 + c1], conv_w[(j + 1) * 128 + c1]);
        }
        wp0[kh * 5 + 4] = pk2(conv_w[(kh * 9 + 8) * 128 + c0], 0.f);
        wp1[kh * 5 + 4] = pk2(conv_w[(kh * 9 + 8) * 128 + c1], 0.f);
    }
    const unsigned long long cbp0 = pk2(conv_b[c0], 0.f);
    const unsigned long long cbp1 = pk2(conv_b[c1], 0.f);

    const unsigned sbase = (unsigned)__cvta_generic_to_shared(in_s);

    __syncthreads();

    // ---- Main loop: grp handles oh rows (qq*8 + grp*2) .. +1, 16 pairs each ----
    float fsum0 = 0.f, fsum1 = 0.f;
    float pacc  = 0.f;
    float ba0 = 0.f, ba1 = 0.f, ba2 = 0.f;

    const float4* __restrict__ bwp = g_bw4 + ((qq * 8 + grp * 2) * 32) * 128;

    for (int ohl = 0; ohl < 2; ++ohl) {
        // local input row = 4*grp + 2*ohl
        unsigned rowa = sbase + (unsigned)((4 * grp + 2 * ohl) * ROW_BYTES);
#pragma unroll 4
        for (int owp = 0; owp < 16; ++owp) {
            // One LDG.128 per (pos, ch), issued first (conv math hides L2 lat).
            const float4 bA0 = __ldg(bwp + c0);
            const float4 bA1 = __ldg(bwp + c1);
            const float4 bB0 = __ldg(bwp + 128 + c0);
            const float4 bB1 = __ldg(bwp + 128 + c1);
            bwp += 256;

            // Conv: 4 independent FFMA2 chains; 4x LDS.128 per kh row.
            unsigned long long aA0 = cbp0, aA1 = cbp1, aB0 = cbp0, aB1 = cbp1;
            unsigned ra = rowa;
#pragma unroll
            for (int kh = 0; kh < 3; ++kh) {
                unsigned long long v0, v1, v2, v3, v4, v5, v6, v7;
                lds128v2(ra,      v0, v1);
                lds128v2(ra + 16, v2, v3);
                lds128v2(ra + 32, v4, v5);
                lds128v2(ra + 48, v6, v7);
                ra += ROW_BYTES;
                // pos A: floats 0..9 -> v0..v4
                aA0 = ffma2(v0, wp0[kh * 5 + 0], aA0);
                aA1 = ffma2(v0, wp1[kh * 5 + 0], aA1);
                aA0 = ffma2(v1, wp0[kh * 5 + 1], aA0);
                aA1 = ffma2(v1, wp1[kh * 5 + 1], aA1);
                aA0 = ffma2(v2, wp0[kh * 5 + 2], aA0);
                aA1 = ffma2(v2, wp1[kh * 5 + 2], aA1);
                aA0 = ffma2(v3, wp0[kh * 5 + 3], aA0);
                aA1 = ffma2(v3, wp1[kh * 5 + 3], aA1);
                aA0 = ffma2(v4, wp0[kh * 5 + 4], aA0);
                aA1 = ffma2(v4, wp1[kh * 5 + 4], aA1);
                // pos B: floats 6..15 -> v3..v7 (same weights)
                aB0 = ffma2(v3, wp0[kh * 5 + 0], aB0);
                aB1 = ffma2(v3, wp1[kh * 5 + 0], aB1);
                aB0 = ffma2(v4, wp0[kh * 5 + 1], aB0);
                aB1 = ffma2(v4, wp1[kh * 5 + 1], aB1);
                aB0 = ffma2(v5, wp0[kh * 5 + 2], aB0);
                aB1 = ffma2(v5, wp1[kh * 5 + 2], aB1);
                aB0 = ffma2(v6, wp0[kh * 5 + 3], aB0);
                aB1 = ffma2(v6, wp1[kh * 5 + 3], aB1);
                aB0 = ffma2(v7, wp0[kh * 5 + 4], aB0);
                aB1 = ffma2(v7, wp1[kh * 5 + 4], aB1);
            }
            rowa += 48;

            float lA0, hA0, lA1, hA1, lB0, hB0, lB1, hB1;
            upk2(aA0, lA0, hA0);
            upk2(aA1, lA1, hA1);
            upk2(aB0, lB0, hB0);
            upk2(aB1, lB1, hB1);
            const float fA0 = fmaxf(lA0 + hA0, 0.f);
            const float fA1 = fmaxf(lA1 + hA1, 0.f);
            const float fB0 = fmaxf(lB0 + hB0, 0.f);
            const float fB1 = fmaxf(lB1 + hB1, 0.f);

            fsum0 += fA0 + fB0;
            fsum1 += fA1 + fB1;

            ba0 = fmaf(fA0, bA0.x, ba0);  ba1 = fmaf(fA0, bA0.y, ba1);
            ba2 = fmaf(fA0, bA0.z, ba2);  pacc = fmaf(fA0, bA0.w, pacc);
            ba0 = fmaf(fA1, bA1.x, ba0);  ba1 = fmaf(fA1, bA1.y, ba1);
            ba2 = fmaf(fA1, bA1.z, ba2);  pacc = fmaf(fA1, bA1.w, pacc);
            ba0 = fmaf(fB0, bB0.x, ba0);  ba1 = fmaf(fB0, bB0.y, ba1);
            ba2 = fmaf(fB0, bB0.z, ba2);  pacc = fmaf(fB0, bB0.w, pacc);
            ba0 = fmaf(fB1, bB1.x, ba0);  ba1 = fmaf(fB1, bB1.y, ba1);
            ba2 = fmaf(fB1, bB1.z, ba2);  pacc = fmaf(fB1, bB1.w, pacc);
        }
    }

    // ---- Block reduction of 5 scalars (deterministic tree) ----
    float v0 = fsum0 * match_w[c0] + fsum1 * match_w[c1];
    float v1 = pacc, v2 = ba0, v3 = ba1, v4 = ba2;
#pragma unroll
    for (int off = 16; off > 0; off >>= 1) {
        v0 += __shfl_down_sync(0xffffffffu, v0, off);
        v1 += __shfl_down_sync(0xffffffffu, v1, off);
        v2 += __shfl_down_sync(0xffffffffu, v2, off);
        v3 += __shfl_down_sync(0xffffffffu, v3, off);
        v4 += __shfl_down_sync(0xffffffffu, v4, off);
    }
    const int warp = tid >> 5;
    const int lane = tid & 31;
    if (lane == 0) {
        red[warp][0] = v0; red[warp][1] = v1; red[warp][2] = v2;
        red[warp][3] = v3; red[warp][4] = v4;
    }
    __syncthreads();

    if (tid == 0) {
        float s0 = 0.f, s1 = 0.f, s2 = 0.f, s3 = 0.f, s4v = 0.f;
#pragma unroll
        for (int w = 0; w < 8; ++w) {
            s0 += red[w][0]; s1 += red[w][1]; s2 += red[w][2];
            s3 += red[w][3]; s4v += red[w][4];
        }
        float* p = g_part + blockIdx.x * 5;
        p[0] = s0; p[1] = s1; p[2] = s2; p[3] = s3; p[4] = s4v;
    }
}

// ---- Combine kernel: 1 block, 256 threads; sum quarters + heads ----
__global__ void __launch_bounds__(256) combine_kernel(
    const float* __restrict__ match_b,  // [1]
    const float* __restrict__ pat_b,    // [1]
    const float* __restrict__ base_b,   // [3]
    float* __restrict__ out)            // [256,3]
{
    const int b = threadIdx.x;          // sample
    const float* p = g_part + (b * 4) * 5;
    // fixed quarter order -> deterministic
    float s0 = 0.f, s1 = 0.f, s2 = 0.f, s3 = 0.f, s4v = 0.f;
#pragma unroll
    for (int q = 0; q < 4; ++q) {
        s0  += p[q * 5 + 0];
        s1  += p[q * 5 + 1];
        s2  += p[q * 5 + 2];
        s3  += p[q * 5 + 3];
        s4v += p[q * 5 + 4];
    }
    const float matchv = s0 * (1.0f / 1024.0f) + match_b[0];
    const float plog = s1 + pat_b[0];
    const float pp = 1.0f / (1.0f + expf(-plog));
    const float l0 = s2 + base_b[0];
    const float l1 = s3 + base_b[1];
    const float l2 = s4v + base_b[2];
    const float mx = fmaxf(l0, fmaxf(l1, l2));
    const float e0 = expf(l0 - mx);
    const float e1 = expf(l1 - mx);
    const float e2 = expf(l2 - mx);
    const float inv = 1.0f / (e0 + e1 + e2);

    float o0, o1, o2;
    if (matchv > 0.0f && plog >= 0.0f) {
        o0 = pp;
        o1 = 0.5f * (1.0f - pp);
        o2 = o1;
    } else {
        o0 = e0 * inv;
        o1 = e1 * inv;
        o2 = e2 * inv;
    }
    out[b * 3 + 0] = o0;
    out[b * 3 + 1] = o1;
    out[b * 3 + 2] = o2;
}

extern "C" void kernel_launch(void* const* d_in, const int* in_sizes, int n_in,
                              void* d_out, int out_size)
{
    (void)in_sizes; (void)n_in; (void)out_size;
    const float* g_in    = (const float*)d_in[0];
    const float* conv_w  = (const float*)d_in[1];
    const float* conv_b  = (const float*)d_in[2];
    const float* match_w = (const float*)d_in[3];
    const float* match_b = (const float*)d_in[4];
    const float* pat_w   = (const float*)d_in[5];
    const float* pat_b   = (const float*)d_in[6];
    const float* base_w  = (const float*)d_in[7];
    const float* base_b  = (const float*)d_in[8];
    const int*   psi     = (const int*)d_in[9];
    float* out = (float*)d_out;

    prep_kernel<<<512, 256>>>(base_w, pat_w, psi);

    pattern_branch_kernel<<<1024, NTHREADS, SMEM_BYTES>>>(
        g_in, conv_w, conv_b, match_w);

    combine_kernel<<<1, 256>>>(match_b, pat_b, base_b, out);
}